// round 2
// baseline (speedup 1.0000x reference)
#include <cuda_runtime.h>
#include <cuda_bf16.h>

#define HH 512
#define WW 512
#define NPIX (HH * WW)
#define NITER 100
#define NBLK 128
#define NTHR 512
#define STRIDE (NBLK * NTHR)   // 65536
#define PPT 4                  // 128*512*4 == 262144 exactly -> no bounds checks

// Persistent-kernel state. Replay-safe by construction:
//  - g_arrive[] counters are monotonic (never reset). After a complete launch
//    every slot equals NBLK * (#launches so far), so the per-launch base is the
//    pre-launch value of ANY slot. We read g_arrive[NITER-1] at block entry:
//    it cannot be modified until all blocks have passed 99 full barriers,
//    which requires every block to have entered -> all blocks read equal base.
//  - g_part is double-buffered (it&1): a block can only overwrite its slot in
//    buffer b at iteration it+2, which requires the it+1 barrier, which
//    requires every block to have finished READING buffer b for iteration it.
__device__ unsigned g_arrive[NITER];
__device__ float4 g_part[2][NBLK];

// Bilinear sample, PyTorch grid_sample(zeros, align_corners=False) semantics,
// matching the reference's masked-gather formulation; returns d tr/d ix, d tr/d iy.
__device__ __forceinline__ void sample(const float* __restrict__ mov,
                                       float ixf, float iyf,
                                       float& tr, float& dtdx, float& dtdy) {
    float x0f = floorf(ixf), y0f = floorf(iyf);
    float wx1 = ixf - x0f,   wy1 = iyf - y0f;
    float wx0 = 1.0f - wx1,  wy0 = 1.0f - wy1;
    float x1f = x0f + 1.0f,  y1f = y0f + 1.0f;
    bool bx0 = (x0f >= 0.0f) && (x0f <= 511.0f);
    bool bx1 = (x1f >= 0.0f) && (x1f <= 511.0f);
    bool by0 = (y0f >= 0.0f) && (y0f <= 511.0f);
    bool by1 = (y1f >= 0.0f) && (y1f <= 511.0f);
    int xi0 = (int)fminf(fmaxf(x0f, 0.0f), 511.0f);
    int xi1 = (int)fminf(fmaxf(x1f, 0.0f), 511.0f);
    int yi0 = (int)fminf(fmaxf(y0f, 0.0f), 511.0f);
    int yi1 = (int)fminf(fmaxf(y1f, 0.0f), 511.0f);
    float v00 = (bx0 && by0) ? __ldg(mov + yi0 * WW + xi0) : 0.0f;
    float v01 = (bx1 && by0) ? __ldg(mov + yi0 * WW + xi1) : 0.0f;
    float v10 = (bx0 && by1) ? __ldg(mov + yi1 * WW + xi0) : 0.0f;
    float v11 = (bx1 && by1) ? __ldg(mov + yi1 * WW + xi1) : 0.0f;
    float m0 = wx0 * v00 + wx1 * v01;
    float m1 = wx0 * v10 + wx1 * v11;
    tr   = wy0 * m0 + wy1 * m1;
    dtdx = wy0 * (v01 - v00) + wy1 * (v11 - v10);
    dtdy = m1 - m0;
}

__global__ void __launch_bounds__(NTHR, 1)
reg_kernel(const float* __restrict__ mov, const float* __restrict__ fix,
           const float* __restrict__ scale0, const float* __restrict__ rot0,
           const float* __restrict__ trans0, float* __restrict__ out) {
    __shared__ float shp[8];        // A=sc*c, B=sc*s, c, s, tx, ty, sc, r
    __shared__ float red[16][4];    // per-warp fp32 partials
    __shared__ double dred[4][4];   // cross-warp fp64 partials (warps 0..3)

    const int tid  = threadIdx.x;
    const int bid  = blockIdx.x;
    const int gid  = bid * NTHR + tid;
    const int lane = tid & 31;
    const int wid  = tid >> 5;

    unsigned base = 0;
    if (tid == 0) {
        base = *(volatile unsigned*)&g_arrive[NITER - 1];   // per-launch base
        float sc = scale0[0], r = rot0[0];
        float tx = trans0[0], ty = trans0[1];
        float cc = cosf(r), ss = sinf(r);
        shp[0] = sc * cc; shp[1] = sc * ss; shp[2] = cc; shp[3] = ss;
        shp[4] = tx; shp[5] = ty; shp[6] = sc; shp[7] = r;
    }

    // Iteration-invariant per-pixel data in registers (exact grid fit).
    float pxj[PPT], pyv[PPT], pfx[PPT];
#pragma unroll
    for (int k = 0; k < PPT; k++) {
        int p = gid + k * STRIDE;
        int i = p >> 9, j = p & 511;
        pxj[k] = ((float)j + 0.5f) * (2.0f / 512.0f) - 1.0f;
        pyv[k] = ((float)i + 0.5f) * (2.0f / 512.0f) - 1.0f;
        pfx[k] = fix[p];
    }
    __syncthreads();

    for (int it = 0; it < NITER; it++) {
        float A = shp[0], B = shp[1], c = shp[2], s = shp[3];
        float tx = shp[4], ty = shp[5];

        float a0 = 0.f, a1 = 0.f, a2 = 0.f, a3 = 0.f;
#pragma unroll
        for (int k = 0; k < PPT; k++) {
            float xj = pxj[k], yv = pyv[k];
            float gx = A * xj - B * yv + tx;
            float gy = B * xj + A * yv + ty;
            float ixf = ((gx + 1.0f) * 512.0f - 1.0f) * 0.5f;
            float iyf = ((gy + 1.0f) * 512.0f - 1.0f) * 0.5f;
            float tr, dtdx, dtdy;
            sample(mov, ixf, iyf, tr, dtdx, dtdy);
            float resid = tr - pfx[k];
            float dgxds = c * xj - s * yv;
            float dgyds = s * xj + c * yv;
            float rx = resid * dtdx;
            float ry = resid * dtdy;
            a2 += rx;
            a3 += ry;
            a0 += rx * dgxds + ry * dgyds;
            a1 += ry * dgxds - rx * dgyds;   // * sc applied at the update
        }

        // intra-warp reduce
#pragma unroll
        for (int off = 16; off > 0; off >>= 1) {
            a0 += __shfl_down_sync(0xFFFFFFFFu, a0, off);
            a1 += __shfl_down_sync(0xFFFFFFFFu, a1, off);
            a2 += __shfl_down_sync(0xFFFFFFFFu, a2, off);
            a3 += __shfl_down_sync(0xFFFFFFFFu, a3, off);
        }
        if (lane == 0) {
            red[wid][0] = a0; red[wid][1] = a1; red[wid][2] = a2; red[wid][3] = a3;
        }
        __syncthreads();
        if (tid < 16) {
            float b0 = red[tid][0], b1 = red[tid][1], b2 = red[tid][2], b3 = red[tid][3];
#pragma unroll
            for (int off = 8; off > 0; off >>= 1) {
                b0 += __shfl_down_sync(0x0000FFFFu, b0, off);
                b1 += __shfl_down_sync(0x0000FFFFu, b1, off);
                b2 += __shfl_down_sync(0x0000FFFFu, b2, off);
                b3 += __shfl_down_sync(0x0000FFFFu, b3, off);
            }
            if (tid == 0) {
                // publish block partial: ONE uncontended STG.128
                g_part[it & 1][bid] = make_float4(b0, b1, b2, b3);
                __threadfence();
                unsigned old = atomicAdd(&g_arrive[it], 1u);
                if (old - base != (unsigned)(NBLK - 1)) {
                    while (*(volatile unsigned*)&g_arrive[it] - base < (unsigned)NBLK) { }
                }
                __threadfence();   // acquire: partials now visible
            }
        }
        __syncthreads();

        // every block redundantly reduces the 128 partials (fp64) and updates
        if (tid < NBLK) {
            float4 v = __ldcg(&g_part[it & 1][tid]);
            double d0 = (double)v.x, d1 = (double)v.y, d2 = (double)v.z, d3 = (double)v.w;
#pragma unroll
            for (int off = 16; off > 0; off >>= 1) {
                d0 += __shfl_down_sync(0xFFFFFFFFu, d0, off);
                d1 += __shfl_down_sync(0xFFFFFFFFu, d1, off);
                d2 += __shfl_down_sync(0xFFFFFFFFu, d2, off);
                d3 += __shfl_down_sync(0xFFFFFFFFu, d3, off);
            }
            if (lane == 0) {
                dred[wid][0] = d0; dred[wid][1] = d1; dred[wid][2] = d2; dred[wid][3] = d3;
            }
        }
        __syncthreads();
        if (tid == 0) {
            double d0 = dred[0][0] + dred[1][0] + dred[2][0] + dred[3][0];
            double d1 = dred[0][1] + dred[1][1] + dred[2][1] + dred[3][1];
            double d2 = dred[0][2] + dred[1][2] + dred[2][2] + dred[3][2];
            double d3 = dred[0][3] + dred[1][3] + dred[2][3] + dred[3][3];
            float sc = shp[6], r = shp[7];
            float txc = shp[4], tyc = shp[5];
            // g = (2/N) * 256 * sum = sum / 512
            float gs  = (float)(d0 * (1.0 / 512.0));
            float gr  = (float)(d1 * (double)sc * (1.0 / 512.0));
            float gtx = (float)(d2 * (1.0 / 512.0));
            float gty = (float)(d3 * (1.0 / 512.0));
            sc  -= gs;  r   -= gr;
            txc -= gtx; tyc -= gty;   // LR = 1
            float cc = cosf(r), ss = sinf(r);
            shp[0] = sc * cc; shp[1] = sc * ss; shp[2] = cc; shp[3] = ss;
            shp[4] = txc; shp[5] = tyc; shp[6] = sc; shp[7] = r;
        }
        __syncthreads();
    }

    // Final transform with post-100-step params.
    {
        float A = shp[0], B = shp[1], tx = shp[4], ty = shp[5];
#pragma unroll
        for (int k = 0; k < PPT; k++) {
            int p = gid + k * STRIDE;
            float xj = pxj[k], yv = pyv[k];
            float gx = A * xj - B * yv + tx;
            float gy = B * xj + A * yv + ty;
            float ixf = ((gx + 1.0f) * 512.0f - 1.0f) * 0.5f;
            float iyf = ((gy + 1.0f) * 512.0f - 1.0f) * 0.5f;
            float tr, dtdx, dtdy;
            sample(mov, ixf, iyf, tr, dtdx, dtdy);
            out[p] = tr;
        }
    }
}

extern "C" void kernel_launch(void* const* d_in, const int* in_sizes, int n_in,
                              void* d_out, int out_size) {
    const float* mov   = (const float*)d_in[0];
    const float* fix   = (const float*)d_in[1];
    const float* scale = (const float*)d_in[2];
    const float* rot   = (const float*)d_in[3];
    const float* trans = (const float*)d_in[4];
    float* out = (float*)d_out;
    reg_kernel<<<NBLK, NTHR>>>(mov, fix, scale, rot, trans, out);
}

// round 3
// speedup vs baseline: 1.2417x; 1.2417x over previous
#include <cuda_runtime.h>
#include <cuda_bf16.h>

#define HH 512
#define WW 512
#define NPIX (HH * WW)
#define NITER 100
#define NBLK 128
#define NTHR 1024
#define STRIDE (NBLK * NTHR)   // 131072
#define PPT 2                  // 128*1024*2 == 262144 exactly
#define IBAR NITER             // init-barrier slot

// Replay-safe persistent state:
//  - g_arrive[] monotonic counters (never reset). Per-launch base is read from
//    slot NITER-1 at block entry: that slot's first increment requires some
//    block to pass barriers IBAR,0..98, i.e. ALL blocks entered (and thus read
//    their base) first.
//  - g_acc[it] zeroed by block 0 during the init phase (before IBAR barrier),
//    accumulated via RED.ADD.F64, read after barrier `it`, never reused
//    within a launch.
__device__ unsigned g_arrive[NITER + 1];
__device__ double g_acc[NITER][4];

__device__ __forceinline__ void arrive_and_wait(int slot, unsigned base) {
    __threadfence();
    atomicAdd(&g_arrive[slot], 1u);
    while (*(volatile unsigned*)&g_arrive[slot] - base < (unsigned)NBLK) { }
    __threadfence();
}

__global__ void __launch_bounds__(NTHR, 1)
reg_kernel(const float* __restrict__ mov, const float* __restrict__ fix,
           const float* __restrict__ scale0, const float* __restrict__ rot0,
           const float* __restrict__ trans0, float* __restrict__ out) {
    __shared__ float shp[8];      // Ap=256*sc*c, Bp=256*sc*s, TX, TY, sc, r, tx, ty
    __shared__ float red[32][4];  // per-warp partials

    const int tid  = threadIdx.x;
    const int bid  = blockIdx.x;
    const int gid  = bid * NTHR + tid;
    const int lane = tid & 31;
    const int wid  = tid >> 5;

    unsigned base = 0;
    if (tid == 0) {
        base = *(volatile unsigned*)&g_arrive[NITER - 1];
        float sc = scale0[0], r = rot0[0];
        float tx = trans0[0], ty = trans0[1];
        float cc = cosf(r), ss = sinf(r);
        shp[0] = 256.0f * sc * cc; shp[1] = 256.0f * sc * ss;
        shp[2] = 256.0f * tx + 255.5f; shp[3] = 256.0f * ty + 255.5f;
        shp[4] = sc; shp[5] = r; shp[6] = tx; shp[7] = ty;
    }

    // Iteration-invariant per-pixel data in registers (exact grid fit).
    float pxj[PPT], pyv[PPT], pfx[PPT];
#pragma unroll
    for (int k = 0; k < PPT; k++) {
        int p = gid + k * STRIDE;
        int i = p >> 9, j = p & 511;
        pxj[k] = ((float)j + 0.5f) * (2.0f / 512.0f) - 1.0f;
        pyv[k] = ((float)i + 0.5f) * (2.0f / 512.0f) - 1.0f;
        pfx[k] = fix[p];
    }

    // init phase: block 0 zeroes the accumulator slots, then init barrier
    if (bid == 0 && tid < NITER * 4)
        ((double*)g_acc)[tid] = 0.0;
    __syncthreads();
    if (tid == 0) arrive_and_wait(IBAR, base);
    __syncthreads();

    for (int it = 0; it < NITER; it++) {
        const float Ap = shp[0], Bp = shp[1], TX = shp[2], TY = shp[3];

        float a0 = 0.f, a1 = 0.f, a2 = 0.f, a3 = 0.f;
#pragma unroll
        for (int k = 0; k < PPT; k++) {
            const float xj = pxj[k], yv = pyv[k];
            float ix = fmaf(Ap, xj, fmaf(-Bp, yv, TX));
            float iy = fmaf(Bp, xj, fmaf(Ap, yv, TY));
            float up = ix - TX;           // = 256*sc*(c*xj - s*yv)
            float vp = iy - TY;           // = 256*sc*(s*xj + c*yv)
            int ix0 = __float2int_rd(ix);
            int iy0 = __float2int_rd(iy);
            float wx1 = ix - (float)ix0;
            float wy1 = iy - (float)iy0;
            bool px0 = (unsigned)ix0 < 512u;
            bool px1 = (unsigned)(ix0 + 1) < 512u;
            bool py0 = (unsigned)iy0 < 512u;
            bool py1 = (unsigned)(iy0 + 1) < 512u;
            int a00 = iy0 * 512 + ix0;    // only used when the predicate is true
            float v00 = (px0 && py0) ? __ldg(mov + a00)       : 0.0f;
            float v01 = (px1 && py0) ? __ldg(mov + a00 + 1)   : 0.0f;
            float v10 = (px0 && py1) ? __ldg(mov + a00 + 512) : 0.0f;
            float v11 = (px1 && py1) ? __ldg(mov + a00 + 513) : 0.0f;
            float d0 = v01 - v00;
            float d1 = v11 - v10;
            float m0 = fmaf(wx1, d0, v00);
            float m1 = fmaf(wx1, d1, v10);
            float dtdx = fmaf(wy1, d1 - d0, d0);
            float dtdy = m1 - m0;
            float tr = fmaf(wy1, dtdy, m0);
            float resid = tr - pfx[k];
            float rx = resid * dtdx;
            float ry = resid * dtdy;
            a2 += rx;
            a3 += ry;
            a0 = fmaf(rx, up, a0);
            a0 = fmaf(ry, vp, a0);
            a1 = fmaf(ry, up, a1);
            a1 = fmaf(-rx, vp, a1);
        }

        // intra-warp reduce
#pragma unroll
        for (int off = 16; off > 0; off >>= 1) {
            a0 += __shfl_down_sync(0xFFFFFFFFu, a0, off);
            a1 += __shfl_down_sync(0xFFFFFFFFu, a1, off);
            a2 += __shfl_down_sync(0xFFFFFFFFu, a2, off);
            a3 += __shfl_down_sync(0xFFFFFFFFu, a3, off);
        }
        if (lane == 0) {
            red[wid][0] = a0; red[wid][1] = a1; red[wid][2] = a2; red[wid][3] = a3;
        }
        __syncthreads();
        if (tid < 32) {
            float4 v = *(const float4*)red[tid];
            float b0 = v.x, b1 = v.y, b2 = v.z, b3 = v.w;
#pragma unroll
            for (int off = 16; off > 0; off >>= 1) {
                b0 += __shfl_down_sync(0xFFFFFFFFu, b0, off);
                b1 += __shfl_down_sync(0xFFFFFFFFu, b1, off);
                b2 += __shfl_down_sync(0xFFFFFFFFu, b2, off);
                b3 += __shfl_down_sync(0xFFFFFFFFu, b3, off);
            }
            if (tid == 0) {
                // fire-and-forget fp64 REDs (return value unused)
                atomicAdd(&g_acc[it][0], (double)b0);
                atomicAdd(&g_acc[it][1], (double)b1);
                atomicAdd(&g_acc[it][2], (double)b2);
                atomicAdd(&g_acc[it][3], (double)b3);
                arrive_and_wait(it, base);
                // all REDs visible; compute the update redundantly per block
                double s0 = *(volatile double*)&g_acc[it][0];
                double s1 = *(volatile double*)&g_acc[it][1];
                double s2 = *(volatile double*)&g_acc[it][2];
                double s3 = *(volatile double*)&g_acc[it][3];
                float sc = shp[4], r = shp[5], tx = shp[6], ty = shp[7];
                // gs = raw0 / (512*256*sc); gr = raw1 / (512*256); gt = raw/512
                float gs  = (float)(s0 / (131072.0 * (double)sc));
                float gr  = (float)(s1 * (1.0 / 131072.0));
                float gtx = (float)(s2 * (1.0 / 512.0));
                float gty = (float)(s3 * (1.0 / 512.0));
                sc -= gs; r -= gr; tx -= gtx; ty -= gty;  // LR = 1
                float cc = cosf(r), ss = sinf(r);
                shp[0] = 256.0f * sc * cc; shp[1] = 256.0f * sc * ss;
                shp[2] = 256.0f * tx + 255.5f; shp[3] = 256.0f * ty + 255.5f;
                shp[4] = sc; shp[5] = r; shp[6] = tx; shp[7] = ty;
            }
        }
        __syncthreads();
    }

    // Final transform with post-100-step params.
    {
        const float Ap = shp[0], Bp = shp[1], TX = shp[2], TY = shp[3];
#pragma unroll
        for (int k = 0; k < PPT; k++) {
            int p = gid + k * STRIDE;
            const float xj = pxj[k], yv = pyv[k];
            float ix = fmaf(Ap, xj, fmaf(-Bp, yv, TX));
            float iy = fmaf(Bp, xj, fmaf(Ap, yv, TY));
            int ix0 = __float2int_rd(ix);
            int iy0 = __float2int_rd(iy);
            float wx1 = ix - (float)ix0;
            float wy1 = iy - (float)iy0;
            bool px0 = (unsigned)ix0 < 512u;
            bool px1 = (unsigned)(ix0 + 1) < 512u;
            bool py0 = (unsigned)iy0 < 512u;
            bool py1 = (unsigned)(iy0 + 1) < 512u;
            int a00 = iy0 * 512 + ix0;
            float v00 = (px0 && py0) ? __ldg(mov + a00)       : 0.0f;
            float v01 = (px1 && py0) ? __ldg(mov + a00 + 1)   : 0.0f;
            float v10 = (px0 && py1) ? __ldg(mov + a00 + 512) : 0.0f;
            float v11 = (px1 && py1) ? __ldg(mov + a00 + 513) : 0.0f;
            float d0 = v01 - v00;
            float d1 = v11 - v10;
            float m0 = fmaf(wx1, d0, v00);
            float m1 = fmaf(wx1, d1, v10);
            float tr = fmaf(wy1, m1 - m0, m0);
            out[p] = tr;
        }
    }
}

extern "C" void kernel_launch(void* const* d_in, const int* in_sizes, int n_in,
                              void* d_out, int out_size) {
    const float* mov   = (const float*)d_in[0];
    const float* fix   = (const float*)d_in[1];
    const float* scale = (const float*)d_in[2];
    const float* rot   = (const float*)d_in[3];
    const float* trans = (const float*)d_in[4];
    float* out = (float*)d_out;
    reg_kernel<<<NBLK, NTHR>>>(mov, fix, scale, rot, trans, out);
}